// round 1
// baseline (speedup 1.0000x reference)
#include <cuda_runtime.h>
#include <cuda_bf16.h>
#include <float.h>

// Problem constants
#define BB 32
#define SS 2048
#define DD 1024
#define EE 16
#define KK 4
#define OO 1024
#define KD 4096   // KK*DD

typedef unsigned long long ULL;

// ---------------- scratch (device globals: no runtime allocation) ----------------
__device__ float g_logits[BB * EE * SS];   // [B][E][S] transposed logits, 4 MB
__device__ float g_inp[BB * EE * KD];      // [B][E][4096], 8 MB
__device__ float g_h1[BB * EE * OO];       // 2 MB
__device__ float g_h2[BB * EE * OO];       // 2 MB

// ---------------- packed f32x2 helpers ----------------
__device__ __forceinline__ void fma2(ULL& d, ULL a, ULL b) {
    asm("fma.rn.f32x2 %0, %1, %2, %0;" : "+l"(d) : "l"(a), "l"(b));
}
__device__ __forceinline__ ULL dup2(float w) {
    ULL r; asm("mov.b64 %0, {%1, %1};" : "=l"(r) : "f"(w)); return r;
}
__device__ __forceinline__ float2 unpack2(ULL v) {
    float2 f; asm("mov.b64 {%0, %1}, %2;" : "=f"(f.x), "=f"(f.y) : "l"(v)); return f;
}

// ---------------- 1) gate GEMM: logits[B,E,S] = (x @ Wg + bg)^T ----------------
// CTA: 128 tokens x 16 experts, K chunked by 32. 256 threads.
// Thread tile: 4 tokens (2 f32x2 pairs) x 2 experts.
__global__ void gate_kernel(const float* __restrict__ x,
                            const float* __restrict__ Wg,
                            const float* __restrict__ bg) {
    __shared__ __align__(16) float As[32][132];   // [k][token], pad 132
    __shared__ __align__(16) float Wgs[32][16];   // [k][e]

    int tid = threadIdx.x;
    int t0 = blockIdx.x * 128;           // global token base (whole CTA in one b)
    int b  = t0 >> 11;                   // t0 / 2048
    int s0 = t0 & 2047;

    int kq = (tid & 7) * 4;              // k offset for staging loads
    int am = tid >> 3;                   // token-within-pass 0..31
    int tx = tid & 7;                    // e-group
    int ty = tid >> 3;                   // token-group 0..31
    int e0 = tx * 2;
    int m0 = ty * 4;

    ULL acc[2][2];
    acc[0][0] = acc[0][1] = acc[1][0] = acc[1][1] = 0ULL;

    for (int c = 0; c < DD / 32; ++c) {
        int kc = c * 32;
        __syncthreads();
        // stage x chunk: 128 tokens x 32 k (transposed into As[k][m])
        #pragma unroll
        for (int p = 0; p < 4; ++p) {
            int m = am + p * 32;
            float4 v = *(const float4*)&x[(size_t)(t0 + m) * DD + kc + kq];
            As[kq + 0][m] = v.x; As[kq + 1][m] = v.y;
            As[kq + 2][m] = v.z; As[kq + 3][m] = v.w;
        }
        // stage Wg chunk: 32 k x 16 e
        if (tid < 128) {
            int kk = tid >> 2, e4 = (tid & 3) * 4;
            *(float4*)&Wgs[kk][e4] = *(const float4*)&Wg[(size_t)(kc + kk) * EE + e4];
        }
        __syncthreads();
        #pragma unroll
        for (int k = 0; k < 32; ++k) {
            ulonglong2 a = *(const ulonglong2*)&As[k][m0];    // 4 tokens = 2 pairs
            float2 wv = *(const float2*)&Wgs[k][e0];
            ULL w0 = dup2(wv.x), w1 = dup2(wv.y);
            fma2(acc[0][0], a.x, w0); fma2(acc[1][0], a.y, w0);
            fma2(acc[0][1], a.x, w1); fma2(acc[1][1], a.y, w1);
        }
    }
    // epilogue: + bg, write transposed [B][E][S]
    #pragma unroll
    for (int j = 0; j < 2; ++j) {
        float bb = bg[e0 + j];
        #pragma unroll
        for (int p = 0; p < 2; ++p) {
            float2 v = unpack2(acc[p][j]);
            int s = s0 + m0 + 2 * p;
            float* dst = &g_logits[((size_t)(b * EE) + e0 + j) * SS + s];
            dst[0] = v.x + bb;
            dst[1] = v.y + bb;
        }
    }
}

// ---------------- 2) softmax(+top4) + gather: one block per (e,b) ----------------
__global__ void topk_gather_kernel(const float* __restrict__ x) {
    int e = blockIdx.x, b = blockIdx.y;
    __shared__ float sv[SS];
    __shared__ float red[256];
    __shared__ int   redi[256];
    __shared__ float s_max, s_sum;
    __shared__ int   s_idx[KK];
    __shared__ float s_val[KK];
    int tid = threadIdx.x;

    const float* row = &g_logits[(size_t)(b * EE + e) * SS];
    float lmax = -FLT_MAX;
    for (int i = tid; i < SS; i += 256) {
        float v = row[i];
        sv[i] = v;
        lmax = fmaxf(lmax, v);
    }
    red[tid] = lmax;
    __syncthreads();
    for (int off = 128; off > 0; off >>= 1) {
        if (tid < off) red[tid] = fmaxf(red[tid], red[tid + off]);
        __syncthreads();
    }
    if (tid == 0) s_max = red[0];
    __syncthreads();
    float mx = s_max;

    float lsum = 0.f;
    for (int i = tid; i < SS; i += 256) lsum += expf(sv[i] - mx);
    red[tid] = lsum;
    __syncthreads();
    for (int off = 128; off > 0; off >>= 1) {
        if (tid < off) red[tid] += red[tid + off];
        __syncthreads();
    }
    if (tid == 0) s_sum = red[0];
    __syncthreads();
    float inv = 1.0f / s_sum;

    // 4 iterations of block-argmax (ties -> lowest index, matching top_k)
    for (int it = 0; it < KK; ++it) {
        float bv = -FLT_MAX;
        int bi = SS;
        for (int i = tid; i < SS; i += 256) {
            float v = sv[i];
            if (v > bv) { bv = v; bi = i; }
        }
        red[tid] = bv; redi[tid] = bi;
        __syncthreads();
        for (int off = 128; off > 0; off >>= 1) {
            if (tid < off) {
                float v2 = red[tid + off]; int i2 = redi[tid + off];
                if (v2 > red[tid] || (v2 == red[tid] && i2 < redi[tid])) {
                    red[tid] = v2; redi[tid] = i2;
                }
            }
            __syncthreads();
        }
        if (tid == 0) {
            int wi = redi[0];
            s_idx[it] = wi;
            s_val[it] = expf(red[0] - mx) * inv;
            sv[wi] = -FLT_MAX;
        }
        __syncthreads();
    }

    // gather: inp[b][e][j*D + d] = x[b][idx_j][d] * prob_j
    #pragma unroll
    for (int j = 0; j < KK; ++j) {
        int idx = s_idx[j];
        float w = s_val[j];
        const float4* src = (const float4*)&x[((size_t)b * SS + idx) * DD];
        float4* dst = (float4*)&g_inp[((size_t)(b * EE + e)) * KD + j * DD];
        for (int d = tid; d < DD / 4; d += 256) {
            float4 v = src[d];
            v.x *= w; v.y *= w; v.z *= w; v.w *= w;
            dst[d] = v;
        }
    }
}

// ---------------- 3) expert GEMM (M=32, N tile 128, f32x2 packed over M) --------
// MODE 0: A=g_inp (K=4096) -> g_h1, relu
// MODE 1: A=g_h1  (K=1024) -> g_h2, relu
// MODE 2: A=g_h2  (K=1024) -> Oext, no relu
template<int MODE, bool RELU>
__global__ void expert_gemm_kernel(const float* __restrict__ W,
                                   const float* __restrict__ bias,
                                   float* __restrict__ Oext, int K) {
    int e = blockIdx.y, nt = blockIdx.x;

    const float* A; float* O; int Ast;
    if (MODE == 0)      { A = g_inp + (size_t)e * KD; Ast = EE * KD; O = g_h1 + (size_t)e * OO; }
    else if (MODE == 1) { A = g_h1  + (size_t)e * OO; Ast = EE * OO; O = g_h2 + (size_t)e * OO; }
    else                { A = g_h2  + (size_t)e * OO; Ast = EE * OO; O = Oext + (size_t)e * OO; }
    const int Ost = EE * OO;

    const float* We = W + (size_t)e * K * OO + nt * 128;
    const float* be = bias + (size_t)e * OO + nt * 128;
    O += nt * 128;

    __shared__ __align__(16) float As[32][36];
    __shared__ __align__(16) float Ws[32][128];

    int tid = threadIdx.x;
    int kq = (tid & 7) * 4, am = tid >> 3;     // A staging map
    int wc = (tid & 31) * 4, wk = tid >> 5;    // W staging map
    int tx = tid & 63, ty = tid >> 6;
    int n0 = tx * 2, m0 = ty * 8;

    ULL acc[4][2];
    #pragma unroll
    for (int p = 0; p < 4; ++p) { acc[p][0] = 0ULL; acc[p][1] = 0ULL; }

    int nch = K >> 5;
    // prefetch chunk 0 into registers
    float4 ra = *(const float4*)&A[(size_t)am * Ast + kq];
    float4 rw[4];
    #pragma unroll
    for (int p = 0; p < 4; ++p)
        rw[p] = *(const float4*)&We[(size_t)(wk + 8 * p) * OO + wc];

    for (int c = 0; c < nch; ++c) {
        __syncthreads();
        As[kq + 0][am] = ra.x; As[kq + 1][am] = ra.y;
        As[kq + 2][am] = ra.z; As[kq + 3][am] = ra.w;
        #pragma unroll
        for (int p = 0; p < 4; ++p)
            *(float4*)&Ws[wk + 8 * p][wc] = rw[p];
        __syncthreads();
        if (c + 1 < nch) {
            int kc = (c + 1) * 32;
            ra = *(const float4*)&A[(size_t)am * Ast + kc + kq];
            #pragma unroll
            for (int p = 0; p < 4; ++p)
                rw[p] = *(const float4*)&We[(size_t)(kc + wk + 8 * p) * OO + wc];
        }
        #pragma unroll
        for (int k = 0; k < 32; ++k) {
            ulonglong2 a01 = *(const ulonglong2*)&As[k][m0];       // rows m0..m0+3
            ulonglong2 a23 = *(const ulonglong2*)&As[k][m0 + 4];   // rows m0+4..m0+7
            float2 wv = *(const float2*)&Ws[k][n0];
            ULL w0 = dup2(wv.x), w1 = dup2(wv.y);
            fma2(acc[0][0], a01.x, w0); fma2(acc[1][0], a01.y, w0);
            fma2(acc[2][0], a23.x, w0); fma2(acc[3][0], a23.y, w0);
            fma2(acc[0][1], a01.x, w1); fma2(acc[1][1], a01.y, w1);
            fma2(acc[2][1], a23.x, w1); fma2(acc[3][1], a23.y, w1);
        }
    }

    #pragma unroll
    for (int j = 0; j < 2; ++j) {
        float bb = be[n0 + j];
        #pragma unroll
        for (int p = 0; p < 4; ++p) {
            float2 v = unpack2(acc[p][j]);
            float r0 = v.x + bb, r1 = v.y + bb;
            if (RELU) { r0 = fmaxf(r0, 0.f); r1 = fmaxf(r1, 0.f); }
            O[(size_t)(m0 + 2 * p) * Ost + n0 + j]     = r0;
            O[(size_t)(m0 + 2 * p + 1) * Ost + n0 + j] = r1;
        }
    }
}

// ---------------- launch ----------------
extern "C" void kernel_launch(void* const* d_in, const int* in_sizes, int n_in,
                              void* d_out, int out_size) {
    const float* x  = (const float*)d_in[0];
    const float* Wg = (const float*)d_in[1];
    const float* bg = (const float*)d_in[2];
    const float* W1 = (const float*)d_in[3];
    const float* b1 = (const float*)d_in[4];
    const float* W2 = (const float*)d_in[5];
    const float* b2 = (const float*)d_in[6];
    const float* W3 = (const float*)d_in[7];
    const float* b3 = (const float*)d_in[8];
    float* out = (float*)d_out;

    gate_kernel<<<(BB * SS) / 128, 256>>>(x, Wg, bg);
    topk_gather_kernel<<<dim3(EE, BB), 256>>>(x);
    expert_gemm_kernel<0, true ><<<dim3(OO / 128, EE), 256>>>(W1, b1, nullptr, KD);
    expert_gemm_kernel<1, true ><<<dim3(OO / 128, EE), 256>>>(W2, b2, nullptr, OO);
    expert_gemm_kernel<2, false><<<dim3(OO / 128, EE), 256>>>(W3, b3, out, OO);
}

// round 2
// speedup vs baseline: 1.1208x; 1.1208x over previous
#include <cuda_runtime.h>
#include <cuda_bf16.h>
#include <float.h>

// Problem constants
#define BB 32
#define SS 2048
#define DD 1024
#define EE 16
#define KK 4
#define OO 1024
#define KD 4096   // KK*DD

typedef unsigned long long ULL;

// ---------------- scratch (device globals: no runtime allocation) ----------------
__device__ float g_logits[BB * EE * SS];   // [B][E][S] transposed logits, 4 MB
__device__ float g_inp[BB * EE * KD];      // [B][E][4096], 8 MB
__device__ float g_h1[BB * EE * OO];       // 2 MB
__device__ float g_h2[BB * EE * OO];       // 2 MB

// ---------------- packed f32x2 helpers ----------------
__device__ __forceinline__ void fma2(ULL& d, ULL a, ULL b) {
    asm("fma.rn.f32x2 %0, %1, %2, %0;" : "+l"(d) : "l"(a), "l"(b));
}
__device__ __forceinline__ ULL dup2(float w) {
    ULL r; asm("mov.b64 %0, {%1, %1};" : "=l"(r) : "f"(w)); return r;
}
__device__ __forceinline__ float2 unpack2(ULL v) {
    float2 f; asm("mov.b64 {%0, %1}, %2;" : "=f"(f.x), "=f"(f.y) : "l"(v)); return f;
}

// ---------------- 1) gate GEMM: logits[B,E,S] = (x @ Wg + bg)^T ----------------
// CTA: 128 tokens x 16 experts, 128 threads, K chunked by 32, double-buffered.
// Thread tile: 8 tokens (4 f32x2 pairs) x 2 experts -> 8 fma2 per k-step.
__global__ void gate_kernel(const float* __restrict__ x,
                            const float* __restrict__ Wg,
                            const float* __restrict__ bg) {
    __shared__ __align__(16) float As[2][32][132];   // [buf][k][token]
    __shared__ __align__(16) float Wgs[2][32][16];   // [buf][k][e]

    int tid = threadIdx.x;
    int t0 = blockIdx.x * 128;           // global token base (whole CTA in one b)
    int b  = t0 >> 11;
    int s0 = t0 & 2047;

    int kq = (tid & 7) * 4;              // staging: k offset
    int am = tid >> 3;                   // staging: token group 0..15
    int kk = tid >> 2;                   // Wg staging row
    int e4 = (tid & 3) * 4;
    int tx = tid & 7;                    // compute: e-group
    int ty = tid >> 3;                   // compute: token-group 0..15
    int e0 = tx * 2;
    int m0 = ty * 8;

    ULL acc[4][2];
    #pragma unroll
    for (int p = 0; p < 4; ++p) { acc[p][0] = 0ULL; acc[p][1] = 0ULL; }

    const int nch = DD / 32;             // 32 chunks
    float4 ra[8];
    float4 rwg;

    // prefetch chunk 0
    #pragma unroll
    for (int p = 0; p < 8; ++p)
        ra[p] = *(const float4*)&x[(size_t)(t0 + am + 16 * p) * DD + kq];
    rwg = *(const float4*)&Wg[(size_t)kk * EE + e4];

    // store chunk 0 into buffer 0
    #pragma unroll
    for (int p = 0; p < 8; ++p) {
        int m = am + 16 * p;
        As[0][kq + 0][m] = ra[p].x; As[0][kq + 1][m] = ra[p].y;
        As[0][kq + 2][m] = ra[p].z; As[0][kq + 3][m] = ra[p].w;
    }
    *(float4*)&Wgs[0][kk][e4] = rwg;
    __syncthreads();

    for (int c = 0; c < nch; ++c) {
        int cur = c & 1;
        if (c + 1 < nch) {
            int kc = (c + 1) * 32;
            #pragma unroll
            for (int p = 0; p < 8; ++p)
                ra[p] = *(const float4*)&x[(size_t)(t0 + am + 16 * p) * DD + kc + kq];
            rwg = *(const float4*)&Wg[(size_t)(kc + kk) * EE + e4];
        }
        #pragma unroll
        for (int k = 0; k < 32; ++k) {
            ulonglong2 a01 = *(const ulonglong2*)&As[cur][k][m0];
            ulonglong2 a23 = *(const ulonglong2*)&As[cur][k][m0 + 4];
            float2 wv = *(const float2*)&Wgs[cur][k][e0];
            ULL w0 = dup2(wv.x), w1 = dup2(wv.y);
            fma2(acc[0][0], a01.x, w0); fma2(acc[1][0], a01.y, w0);
            fma2(acc[2][0], a23.x, w0); fma2(acc[3][0], a23.y, w0);
            fma2(acc[0][1], a01.x, w1); fma2(acc[1][1], a01.y, w1);
            fma2(acc[2][1], a23.x, w1); fma2(acc[3][1], a23.y, w1);
        }
        if (c + 1 < nch) {
            int nb = (c + 1) & 1;
            #pragma unroll
            for (int p = 0; p < 8; ++p) {
                int m = am + 16 * p;
                As[nb][kq + 0][m] = ra[p].x; As[nb][kq + 1][m] = ra[p].y;
                As[nb][kq + 2][m] = ra[p].z; As[nb][kq + 3][m] = ra[p].w;
            }
            *(float4*)&Wgs[nb][kk][e4] = rwg;
            __syncthreads();
        }
    }

    // epilogue: + bg, write transposed [B][E][S] as float2 along S
    #pragma unroll
    for (int j = 0; j < 2; ++j) {
        float bb = bg[e0 + j];
        float* dst = &g_logits[((size_t)(b * EE) + e0 + j) * SS];
        #pragma unroll
        for (int p = 0; p < 4; ++p) {
            float2 v = unpack2(acc[p][j]);
            int s = s0 + m0 + 2 * p;
            *(float2*)&dst[s] = make_float2(v.x + bb, v.y + bb);
        }
    }
}

// ---------------- 2) softmax(+top4) + gather: one block per (e,b) ----------------
__global__ void topk_gather_kernel(const float* __restrict__ x) {
    int e = blockIdx.x, b = blockIdx.y;
    __shared__ float sv[SS];
    __shared__ float red[256];
    __shared__ int   redi[256];
    __shared__ float s_max, s_sum;
    __shared__ int   s_idx[KK];
    __shared__ float s_val[KK];
    int tid = threadIdx.x;

    const float* row = &g_logits[(size_t)(b * EE + e) * SS];
    float lmax = -FLT_MAX;
    for (int i = tid; i < SS; i += 256) {
        float v = row[i];
        sv[i] = v;
        lmax = fmaxf(lmax, v);
    }
    red[tid] = lmax;
    __syncthreads();
    for (int off = 128; off > 0; off >>= 1) {
        if (tid < off) red[tid] = fmaxf(red[tid], red[tid + off]);
        __syncthreads();
    }
    if (tid == 0) s_max = red[0];
    __syncthreads();
    float mx = s_max;

    float lsum = 0.f;
    for (int i = tid; i < SS; i += 256) lsum += expf(sv[i] - mx);
    red[tid] = lsum;
    __syncthreads();
    for (int off = 128; off > 0; off >>= 1) {
        if (tid < off) red[tid] += red[tid + off];
        __syncthreads();
    }
    if (tid == 0) s_sum = red[0];
    __syncthreads();
    float inv = 1.0f / s_sum;

    // 4 iterations of block-argmax (ties -> lowest index, matching top_k)
    for (int it = 0; it < KK; ++it) {
        float bv = -FLT_MAX;
        int bi = SS;
        for (int i = tid; i < SS; i += 256) {
            float v = sv[i];
            if (v > bv) { bv = v; bi = i; }
        }
        red[tid] = bv; redi[tid] = bi;
        __syncthreads();
        for (int off = 128; off > 0; off >>= 1) {
            if (tid < off) {
                float v2 = red[tid + off]; int i2 = redi[tid + off];
                if (v2 > red[tid] || (v2 == red[tid] && i2 < redi[tid])) {
                    red[tid] = v2; redi[tid] = i2;
                }
            }
            __syncthreads();
        }
        if (tid == 0) {
            int wi = redi[0];
            s_idx[it] = wi;
            s_val[it] = expf(red[0] - mx) * inv;
            sv[wi] = -FLT_MAX;
        }
        __syncthreads();
    }

    // gather: inp[b][e][j*D + d] = x[b][idx_j][d] * prob_j
    #pragma unroll
    for (int j = 0; j < KK; ++j) {
        int idx = s_idx[j];
        float w = s_val[j];
        const float4* src = (const float4*)&x[((size_t)b * SS + idx) * DD];
        float4* dst = (float4*)&g_inp[((size_t)(b * EE + e)) * KD + j * DD];
        for (int d = tid; d < DD / 4; d += 256) {
            float4 v = src[d];
            v.x *= w; v.y *= w; v.z *= w; v.w *= w;
            dst[d] = v;
        }
    }
}

// ---------------- 3) expert GEMM (M=32, N tile 64, 128 threads, f32x2) --------
// MODE 0: A=g_inp (K=4096) -> g_h1, relu
// MODE 1: A=g_h1  (K=1024) -> g_h2, relu
// MODE 2: A=g_h2  (K=1024) -> Oext, no relu
template<int MODE, bool RELU>
__global__ void expert_gemm_kernel(const float* __restrict__ W,
                                   const float* __restrict__ bias,
                                   float* __restrict__ Oext, int K) {
    int e = blockIdx.y, nt = blockIdx.x;   // 16 tiles of 64 columns

    const float* A; float* O; int Ast;
    if (MODE == 0)      { A = g_inp + (size_t)e * KD; Ast = EE * KD; O = g_h1 + (size_t)e * OO; }
    else if (MODE == 1) { A = g_h1  + (size_t)e * OO; Ast = EE * OO; O = g_h2 + (size_t)e * OO; }
    else                { A = g_h2  + (size_t)e * OO; Ast = EE * OO; O = Oext + (size_t)e * OO; }
    const int Ost = EE * OO;

    const float* We = W + (size_t)e * K * OO + nt * 64;
    const float* be = bias + (size_t)e * OO + nt * 64;
    O += nt * 64;

    __shared__ __align__(16) float As[2][32][36];   // [buf][k][m]
    __shared__ __align__(16) float Ws[2][32][64];   // [buf][k][n]

    int tid = threadIdx.x;
    int kq = (tid & 7) * 4, am = tid >> 3;       // A staging: row am(+16), cols kq..kq+3
    int wc = (tid & 15) * 4, wk = tid >> 4;      // W staging: rows wk+8p, cols wc..wc+3
    int tx = tid & 31, ty = tid >> 5;            // compute map
    int n0 = tx * 2, m0 = ty * 8;

    ULL acc[4][2];
    #pragma unroll
    for (int p = 0; p < 4; ++p) { acc[p][0] = 0ULL; acc[p][1] = 0ULL; }

    const int nch = K >> 5;
    float4 ra[2];
    float4 rw[4];

    // prefetch + store chunk 0
    #pragma unroll
    for (int p = 0; p < 2; ++p)
        ra[p] = *(const float4*)&A[(size_t)(am + 16 * p) * Ast + kq];
    #pragma unroll
    for (int p = 0; p < 4; ++p)
        rw[p] = *(const float4*)&We[(size_t)(wk + 8 * p) * OO + wc];

    #pragma unroll
    for (int p = 0; p < 2; ++p) {
        int m = am + 16 * p;
        As[0][kq + 0][m] = ra[p].x; As[0][kq + 1][m] = ra[p].y;
        As[0][kq + 2][m] = ra[p].z; As[0][kq + 3][m] = ra[p].w;
    }
    #pragma unroll
    for (int p = 0; p < 4; ++p)
        *(float4*)&Ws[0][wk + 8 * p][wc] = rw[p];
    __syncthreads();

    for (int c = 0; c < nch; ++c) {
        int cur = c & 1;
        if (c + 1 < nch) {
            int kc = (c + 1) * 32;
            #pragma unroll
            for (int p = 0; p < 2; ++p)
                ra[p] = *(const float4*)&A[(size_t)(am + 16 * p) * Ast + kc + kq];
            #pragma unroll
            for (int p = 0; p < 4; ++p)
                rw[p] = *(const float4*)&We[(size_t)(kc + wk + 8 * p) * OO + wc];
        }
        #pragma unroll
        for (int k = 0; k < 32; ++k) {
            ulonglong2 a01 = *(const ulonglong2*)&As[cur][k][m0];       // rows m0..m0+3
            ulonglong2 a23 = *(const ulonglong2*)&As[cur][k][m0 + 4];   // rows m0+4..m0+7
            float2 wv = *(const float2*)&Ws[cur][k][n0];
            ULL w0 = dup2(wv.x), w1 = dup2(wv.y);
            fma2(acc[0][0], a01.x, w0); fma2(acc[1][0], a01.y, w0);
            fma2(acc[2][0], a23.x, w0); fma2(acc[3][0], a23.y, w0);
            fma2(acc[0][1], a01.x, w1); fma2(acc[1][1], a01.y, w1);
            fma2(acc[2][1], a23.x, w1); fma2(acc[3][1], a23.y, w1);
        }
        if (c + 1 < nch) {
            int nb = (c + 1) & 1;
            #pragma unroll
            for (int p = 0; p < 2; ++p) {
                int m = am + 16 * p;
                As[nb][kq + 0][m] = ra[p].x; As[nb][kq + 1][m] = ra[p].y;
                As[nb][kq + 2][m] = ra[p].z; As[nb][kq + 3][m] = ra[p].w;
            }
            #pragma unroll
            for (int p = 0; p < 4; ++p)
                *(float4*)&Ws[nb][wk + 8 * p][wc] = rw[p];
            __syncthreads();
        }
    }

    // epilogue: bias (+relu), float2 stores along n
    float b0 = be[n0], b1 = be[n0 + 1];
    #pragma unroll
    for (int p = 0; p < 4; ++p) {
        float2 v0 = unpack2(acc[p][0]);   // col n0,   rows m0+2p, m0+2p+1
        float2 v1 = unpack2(acc[p][1]);   // col n0+1
        float r00 = v0.x + b0, r01 = v1.x + b1;
        float r10 = v0.y + b0, r11 = v1.y + b1;
        if (RELU) {
            r00 = fmaxf(r00, 0.f); r01 = fmaxf(r01, 0.f);
            r10 = fmaxf(r10, 0.f); r11 = fmaxf(r11, 0.f);
        }
        *(float2*)&O[(size_t)(m0 + 2 * p) * Ost + n0]     = make_float2(r00, r01);
        *(float2*)&O[(size_t)(m0 + 2 * p + 1) * Ost + n0] = make_float2(r10, r11);
    }
}

// ---------------- launch ----------------
extern "C" void kernel_launch(void* const* d_in, const int* in_sizes, int n_in,
                              void* d_out, int out_size) {
    const float* x  = (const float*)d_in[0];
    const float* Wg = (const float*)d_in[1];
    const float* bg = (const float*)d_in[2];
    const float* W1 = (const float*)d_in[3];
    const float* b1 = (const float*)d_in[4];
    const float* W2 = (const float*)d_in[5];
    const float* b2 = (const float*)d_in[6];
    const float* W3 = (const float*)d_in[7];
    const float* b3 = (const float*)d_in[8];
    float* out = (float*)d_out;

    gate_kernel<<<(BB * SS) / 128, 128>>>(x, Wg, bg);
    topk_gather_kernel<<<dim3(EE, BB), 256>>>(x);
    expert_gemm_kernel<0, true ><<<dim3(OO / 64, EE), 128>>>(W1, b1, nullptr, KD);
    expert_gemm_kernel<1, true ><<<dim3(OO / 64, EE), 128>>>(W2, b2, nullptr, OO);
    expert_gemm_kernel<2, false><<<dim3(OO / 64, EE), 128>>>(W3, b3, out, OO);
}

// round 3
// speedup vs baseline: 1.2382x; 1.1047x over previous
#include <cuda_runtime.h>
#include <cuda_bf16.h>
#include <float.h>

// Problem constants
#define BB 32
#define SS 2048
#define DD 1024
#define EE 16
#define KK 4
#define OO 1024
#define KD 4096   // KK*DD
#define SPLIT 4

typedef unsigned long long ULL;

// ---------------- scratch (device globals: no runtime allocation) ----------------
__device__ float g_logits[BB * EE * SS];          // [B][E][S] transposed logits, 4 MB
__device__ float g_inp[EE * BB * KD];             // dense [e][b][4096], 8 MB
__device__ float g_h1[EE * BB * OO];              // dense [e][b][1024], 2 MB
__device__ float g_h2[EE * BB * OO];              // 2 MB
__device__ float g_part[SPLIT * EE * BB * OO];    // split-K partials, 8 MB

// ---------------- packed f32x2 helpers ----------------
__device__ __forceinline__ void fma2(ULL& d, ULL a, ULL b) {
    asm("fma.rn.f32x2 %0, %1, %2, %0;" : "+l"(d) : "l"(a), "l"(b));
}
__device__ __forceinline__ ULL dup2(float w) {
    ULL r; asm("mov.b64 %0, {%1, %1};" : "=l"(r) : "f"(w)); return r;
}
__device__ __forceinline__ float2 unpack2(ULL v) {
    float2 f; asm("mov.b64 {%0, %1}, %2;" : "=f"(f.x), "=f"(f.y) : "l"(v)); return f;
}

// ---------------- 1) gate GEMM: logits[B,E,S] = (x @ Wg + bg)^T ----------------
__global__ void gate_kernel(const float* __restrict__ x,
                            const float* __restrict__ Wg,
                            const float* __restrict__ bg) {
    __shared__ __align__(16) float As[2][32][132];   // [buf][k][token]
    __shared__ __align__(16) float Wgs[2][32][16];   // [buf][k][e]

    int tid = threadIdx.x;
    int t0 = blockIdx.x * 128;
    int b  = t0 >> 11;
    int s0 = t0 & 2047;

    int kq = (tid & 7) * 4;
    int am = tid >> 3;
    int kk = tid >> 2;
    int e4 = (tid & 3) * 4;
    int tx = tid & 7;
    int ty = tid >> 3;
    int e0 = tx * 2;
    int m0 = ty * 8;

    ULL acc[4][2];
    #pragma unroll
    for (int p = 0; p < 4; ++p) { acc[p][0] = 0ULL; acc[p][1] = 0ULL; }

    const int nch = DD / 32;
    float4 ra[8];
    float4 rwg;

    #pragma unroll
    for (int p = 0; p < 8; ++p)
        ra[p] = *(const float4*)&x[(size_t)(t0 + am + 16 * p) * DD + kq];
    rwg = *(const float4*)&Wg[(size_t)kk * EE + e4];

    #pragma unroll
    for (int p = 0; p < 8; ++p) {
        int m = am + 16 * p;
        As[0][kq + 0][m] = ra[p].x; As[0][kq + 1][m] = ra[p].y;
        As[0][kq + 2][m] = ra[p].z; As[0][kq + 3][m] = ra[p].w;
    }
    *(float4*)&Wgs[0][kk][e4] = rwg;
    __syncthreads();

    for (int c = 0; c < nch; ++c) {
        int cur = c & 1;
        if (c + 1 < nch) {
            int kc = (c + 1) * 32;
            #pragma unroll
            for (int p = 0; p < 8; ++p)
                ra[p] = *(const float4*)&x[(size_t)(t0 + am + 16 * p) * DD + kc + kq];
            rwg = *(const float4*)&Wg[(size_t)(kc + kk) * EE + e4];
        }
        #pragma unroll
        for (int k = 0; k < 32; ++k) {
            ulonglong2 a01 = *(const ulonglong2*)&As[cur][k][m0];
            ulonglong2 a23 = *(const ulonglong2*)&As[cur][k][m0 + 4];
            float2 wv = *(const float2*)&Wgs[cur][k][e0];
            ULL w0 = dup2(wv.x), w1 = dup2(wv.y);
            fma2(acc[0][0], a01.x, w0); fma2(acc[1][0], a01.y, w0);
            fma2(acc[2][0], a23.x, w0); fma2(acc[3][0], a23.y, w0);
            fma2(acc[0][1], a01.x, w1); fma2(acc[1][1], a01.y, w1);
            fma2(acc[2][1], a23.x, w1); fma2(acc[3][1], a23.y, w1);
        }
        if (c + 1 < nch) {
            int nb = (c + 1) & 1;
            #pragma unroll
            for (int p = 0; p < 8; ++p) {
                int m = am + 16 * p;
                As[nb][kq + 0][m] = ra[p].x; As[nb][kq + 1][m] = ra[p].y;
                As[nb][kq + 2][m] = ra[p].z; As[nb][kq + 3][m] = ra[p].w;
            }
            *(float4*)&Wgs[nb][kk][e4] = rwg;
            __syncthreads();
        }
    }

    #pragma unroll
    for (int j = 0; j < 2; ++j) {
        float bb = bg[e0 + j];
        float* dst = &g_logits[((size_t)(b * EE) + e0 + j) * SS];
        #pragma unroll
        for (int p = 0; p < 4; ++p) {
            float2 v = unpack2(acc[p][j]);
            int s = s0 + m0 + 2 * p;
            *(float2*)&dst[s] = make_float2(v.x + bb, v.y + bb);
        }
    }
}

// ---------------- 2) softmax(+top4) + gather: one block per (e,b) ----------------
__global__ void topk_gather_kernel(const float* __restrict__ x) {
    int e = blockIdx.x, b = blockIdx.y;
    __shared__ float sv[SS];
    __shared__ float red[256];
    __shared__ int   redi[256];
    __shared__ float s_max, s_sum;
    __shared__ int   s_idx[KK];
    __shared__ float s_val[KK];
    int tid = threadIdx.x;

    const float* row = &g_logits[(size_t)(b * EE + e) * SS];
    float lmax = -FLT_MAX;
    for (int i = tid; i < SS; i += 256) {
        float v = row[i];
        sv[i] = v;
        lmax = fmaxf(lmax, v);
    }
    red[tid] = lmax;
    __syncthreads();
    for (int off = 128; off > 0; off >>= 1) {
        if (tid < off) red[tid] = fmaxf(red[tid], red[tid + off]);
        __syncthreads();
    }
    if (tid == 0) s_max = red[0];
    __syncthreads();
    float mx = s_max;

    float lsum = 0.f;
    for (int i = tid; i < SS; i += 256) lsum += expf(sv[i] - mx);
    red[tid] = lsum;
    __syncthreads();
    for (int off = 128; off > 0; off >>= 1) {
        if (tid < off) red[tid] += red[tid + off];
        __syncthreads();
    }
    if (tid == 0) s_sum = red[0];
    __syncthreads();
    float inv = 1.0f / s_sum;

    for (int it = 0; it < KK; ++it) {
        float bv = -FLT_MAX;
        int bi = SS;
        for (int i = tid; i < SS; i += 256) {
            float v = sv[i];
            if (v > bv) { bv = v; bi = i; }
        }
        red[tid] = bv; redi[tid] = bi;
        __syncthreads();
        for (int off = 128; off > 0; off >>= 1) {
            if (tid < off) {
                float v2 = red[tid + off]; int i2 = redi[tid + off];
                if (v2 > red[tid] || (v2 == red[tid] && i2 < redi[tid])) {
                    red[tid] = v2; redi[tid] = i2;
                }
            }
            __syncthreads();
        }
        if (tid == 0) {
            int wi = redi[0];
            s_idx[it] = wi;
            s_val[it] = expf(red[0] - mx) * inv;
            sv[wi] = -FLT_MAX;
        }
        __syncthreads();
    }

    // gather into dense [e][b][j*D + d]
    #pragma unroll
    for (int j = 0; j < KK; ++j) {
        int idx = s_idx[j];
        float w = s_val[j];
        const float4* src = (const float4*)&x[((size_t)b * SS + idx) * DD];
        float4* dst = (float4*)&g_inp[((size_t)(e * BB + b)) * KD + j * DD];
        for (int d = tid; d < DD / 4; d += 256) {
            float4 v = src[d];
            v.x *= w; v.y *= w; v.z *= w; v.w *= w;
            dst[d] = v;
        }
    }
}

// ---------------- 3) expert GEMM partials: M=32, N-tile 64, split-K ----------
// MODE 0: A=g_inp (Ktot=4096), MODE 1: A=g_h1 (1024), MODE 2: A=g_h2 (1024)
// grid = (16 tiles, 16 experts, SPLIT). Partial (no bias) -> g_part.
template<int MODE>
__global__ void __launch_bounds__(128)
expert_gemm_part(const float* __restrict__ W, int Ktot) {
    int e = blockIdx.y, nt = blockIdx.x, ks = blockIdx.z;
    const int Ksub = Ktot / SPLIT;
    const int k0base = ks * Ksub;

    const float* A;
    if (MODE == 0)      A = g_inp + (size_t)e * BB * KD;
    else if (MODE == 1) A = g_h1  + (size_t)e * BB * OO;
    else                A = g_h2  + (size_t)e * BB * OO;
    const int Ast = (MODE == 0) ? KD : OO;

    const float* We = W + (size_t)e * Ktot * OO + nt * 64;
    float* P = g_part + ((size_t)(ks * EE + e) * BB) * OO + nt * 64;

    __shared__ __align__(16) float As[2][32][36];
    __shared__ __align__(16) float Ws[2][32][64];

    int tid = threadIdx.x;
    int kq = (tid & 7) * 4, am = tid >> 3;
    int wc = (tid & 15) * 4, wk = tid >> 4;
    int tx = tid & 31, ty = tid >> 5;
    int n0 = tx * 2, m0 = ty * 8;

    ULL acc[4][2];
    #pragma unroll
    for (int p = 0; p < 4; ++p) { acc[p][0] = 0ULL; acc[p][1] = 0ULL; }

    const int nch = Ksub >> 5;
    float4 ra[2];
    float4 rw[4];

    #pragma unroll
    for (int p = 0; p < 2; ++p)
        ra[p] = *(const float4*)&A[(size_t)(am + 16 * p) * Ast + k0base + kq];
    #pragma unroll
    for (int p = 0; p < 4; ++p)
        rw[p] = *(const float4*)&We[(size_t)(k0base + wk + 8 * p) * OO + wc];

    #pragma unroll
    for (int p = 0; p < 2; ++p) {
        int m = am + 16 * p;
        As[0][kq + 0][m] = ra[p].x; As[0][kq + 1][m] = ra[p].y;
        As[0][kq + 2][m] = ra[p].z; As[0][kq + 3][m] = ra[p].w;
    }
    #pragma unroll
    for (int p = 0; p < 4; ++p)
        *(float4*)&Ws[0][wk + 8 * p][wc] = rw[p];
    __syncthreads();

    for (int c = 0; c < nch; ++c) {
        int cur = c & 1;
        if (c + 1 < nch) {
            int kc = k0base + (c + 1) * 32;
            #pragma unroll
            for (int p = 0; p < 2; ++p)
                ra[p] = *(const float4*)&A[(size_t)(am + 16 * p) * Ast + kc + kq];
            #pragma unroll
            for (int p = 0; p < 4; ++p)
                rw[p] = *(const float4*)&We[(size_t)(kc + wk + 8 * p) * OO + wc];
        }
        #pragma unroll
        for (int k = 0; k < 32; ++k) {
            ulonglong2 a01 = *(const ulonglong2*)&As[cur][k][m0];
            ulonglong2 a23 = *(const ulonglong2*)&As[cur][k][m0 + 4];
            float2 wv = *(const float2*)&Ws[cur][k][n0];
            ULL w0 = dup2(wv.x), w1 = dup2(wv.y);
            fma2(acc[0][0], a01.x, w0); fma2(acc[1][0], a01.y, w0);
            fma2(acc[2][0], a23.x, w0); fma2(acc[3][0], a23.y, w0);
            fma2(acc[0][1], a01.x, w1); fma2(acc[1][1], a01.y, w1);
            fma2(acc[2][1], a23.x, w1); fma2(acc[3][1], a23.y, w1);
        }
        if (c + 1 < nch) {
            int nb = (c + 1) & 1;
            #pragma unroll
            for (int p = 0; p < 2; ++p) {
                int m = am + 16 * p;
                As[nb][kq + 0][m] = ra[p].x; As[nb][kq + 1][m] = ra[p].y;
                As[nb][kq + 2][m] = ra[p].z; As[nb][kq + 3][m] = ra[p].w;
            }
            #pragma unroll
            for (int p = 0; p < 4; ++p)
                *(float4*)&Ws[nb][wk + 8 * p][wc] = rw[p];
            __syncthreads();
        }
    }

    // write partial tile (dense rows, stride OO)
    #pragma unroll
    for (int p = 0; p < 4; ++p) {
        float2 v0 = unpack2(acc[p][0]);
        float2 v1 = unpack2(acc[p][1]);
        *(float2*)&P[(size_t)(m0 + 2 * p) * OO + n0]     = make_float2(v0.x, v1.x);
        *(float2*)&P[(size_t)(m0 + 2 * p + 1) * OO + n0] = make_float2(v0.y, v1.y);
    }
}

// ---------------- 4) split-K reduce: sum partials + bias (+relu) ----------------
// FINAL=false: dst dense [e][b][n]. FINAL=true: dst [b][e][n] (harness output).
template<bool RELU, bool FINAL>
__global__ void reduce_kernel(const float* __restrict__ bias, float* __restrict__ dst) {
    int i = blockIdx.x * 256 + threadIdx.x;    // float4 index over E*B*O/4
    int n4 = i & (OO / 4 - 1);
    int m  = (i >> 8) & (BB - 1);
    int e  = i >> 13;

    const float4* p0 = (const float4*)&g_part[((size_t)(0 * EE + e) * BB + m) * OO];
    float4 a = p0[n4];
    #pragma unroll
    for (int s = 1; s < SPLIT; ++s) {
        float4 v = ((const float4*)&g_part[((size_t)(s * EE + e) * BB + m) * OO])[n4];
        a.x += v.x; a.y += v.y; a.z += v.z; a.w += v.w;
    }
    float4 bb = ((const float4*)&bias[(size_t)e * OO])[n4];
    a.x += bb.x; a.y += bb.y; a.z += bb.z; a.w += bb.w;
    if (RELU) {
        a.x = fmaxf(a.x, 0.f); a.y = fmaxf(a.y, 0.f);
        a.z = fmaxf(a.z, 0.f); a.w = fmaxf(a.w, 0.f);
    }
    if (FINAL)
        ((float4*)&dst[((size_t)m * EE + e) * OO])[n4] = a;
    else
        ((float4*)&dst[((size_t)e * BB + m) * OO])[n4] = a;
}

// ---------------- launch ----------------
extern "C" void kernel_launch(void* const* d_in, const int* in_sizes, int n_in,
                              void* d_out, int out_size) {
    const float* x  = (const float*)d_in[0];
    const float* Wg = (const float*)d_in[1];
    const float* bg = (const float*)d_in[2];
    const float* W1 = (const float*)d_in[3];
    const float* b1 = (const float*)d_in[4];
    const float* W2 = (const float*)d_in[5];
    const float* b2 = (const float*)d_in[6];
    const float* W3 = (const float*)d_in[7];
    const float* b3 = (const float*)d_in[8];
    float* out = (float*)d_out;

    float* h1; cudaGetSymbolAddress((void**)&h1, g_h1);
    float* h2; cudaGetSymbolAddress((void**)&h2, g_h2);

    const int RED_GRID = (EE * BB * OO / 4) / 256;   // 512

    gate_kernel<<<(BB * SS) / 128, 128>>>(x, Wg, bg);
    topk_gather_kernel<<<dim3(EE, BB), 256>>>(x);

    expert_gemm_part<0><<<dim3(OO / 64, EE, SPLIT), 128>>>(W1, KD);
    reduce_kernel<true, false><<<RED_GRID, 256>>>(b1, h1);

    expert_gemm_part<1><<<dim3(OO / 64, EE, SPLIT), 128>>>(W2, OO);
    reduce_kernel<true, false><<<RED_GRID, 256>>>(b2, h2);

    expert_gemm_part<2><<<dim3(OO / 64, EE, SPLIT), 128>>>(W3, OO);
    reduce_kernel<false, true><<<RED_GRID, 256>>>(b3, out);
}

// round 5
// speedup vs baseline: 1.3081x; 1.0564x over previous
#include <cuda_runtime.h>
#include <cuda_bf16.h>
#include <float.h>
#include <cstdint>

// Problem constants
#define BB 32
#define SS 2048
#define DD 1024
#define EE 16
#define KK 4
#define OO 1024
#define KD 4096   // KK*DD
#define SPLIT 4

typedef unsigned long long ULL;

// ---------------- scratch (device globals) ----------------
__device__ float g_logits[BB * EE * SS];            // [B][E][S], 4 MB
__device__ __nv_bfloat16 g_inph[EE * BB * KD];      // inp hi, [e][b][4096]
__device__ __nv_bfloat16 g_inpl[EE * BB * KD];      // inp lo
__device__ __nv_bfloat16 g_h1h[EE * BB * OO];
__device__ __nv_bfloat16 g_h1l[EE * BB * OO];
__device__ __nv_bfloat16 g_h2h[EE * BB * OO];
__device__ __nv_bfloat16 g_h2l[EE * BB * OO];
__device__ float g_part[SPLIT * EE * BB * OO];      // split-K partials, 8 MB

// ---------------- f32x2 helpers (gate kernel) ----------------
__device__ __forceinline__ void fma2(ULL& d, ULL a, ULL b) {
    asm("fma.rn.f32x2 %0, %1, %2, %0;" : "+l"(d) : "l"(a), "l"(b));
}
__device__ __forceinline__ ULL dup2(float w) {
    ULL r; asm("mov.b64 %0, {%1, %1};" : "=l"(r) : "f"(w)); return r;
}
__device__ __forceinline__ float2 unpack2(ULL v) {
    float2 f; asm("mov.b64 {%0, %1}, %2;" : "=f"(f.x), "=f"(f.y) : "l"(v)); return f;
}

// ---------------- bf16 split helper ----------------
// packs (a,b): a -> low half, b -> high half; lo = residual
__device__ __forceinline__ void split2(float a, float b, uint32_t& hi, uint32_t& lo) {
    asm("cvt.rn.satfinite.bf16x2.f32 %0, %1, %2;" : "=r"(hi) : "f"(b), "f"(a));
    __nv_bfloat162 hp = *reinterpret_cast<__nv_bfloat162*>(&hi);
    float r0 = a - __low2float(hp);
    float r1 = b - __high2float(hp);
    asm("cvt.rn.satfinite.bf16x2.f32 %0, %1, %2;" : "=r"(lo) : "f"(r1), "f"(r0));
}

// ---------------- portable tensor-core helpers (sm_80+ PTX) ----------------
__device__ __forceinline__ uint32_t smem_u32(const void* p) {
    uint32_t a;
    asm("{ .reg .u64 t; cvta.to.shared.u64 t, %1; cvt.u32.u64 %0, t; }" : "=r"(a) : "l"(p));
    return a;
}
__device__ __forceinline__ void ldsm4(uint32_t& r0, uint32_t& r1, uint32_t& r2, uint32_t& r3, uint32_t addr) {
    asm volatile("ldmatrix.sync.aligned.m8n8.x4.shared.b16 {%0,%1,%2,%3}, [%4];"
        : "=r"(r0), "=r"(r1), "=r"(r2), "=r"(r3) : "r"(addr));
}
__device__ __forceinline__ void ldsm4t(uint32_t& r0, uint32_t& r1, uint32_t& r2, uint32_t& r3, uint32_t addr) {
    asm volatile("ldmatrix.sync.aligned.m8n8.x4.trans.shared.b16 {%0,%1,%2,%3}, [%4];"
        : "=r"(r0), "=r"(r1), "=r"(r2), "=r"(r3) : "r"(addr));
}
__device__ __forceinline__ void mma16816(float* c, uint32_t a0, uint32_t a1, uint32_t a2, uint32_t a3,
                                         uint32_t b0, uint32_t b1) {
    asm("mma.sync.aligned.m16n8k16.row.col.f32.bf16.bf16.f32 "
        "{%0,%1,%2,%3}, {%4,%5,%6,%7}, {%8,%9}, {%0,%1,%2,%3};"
        : "+f"(c[0]), "+f"(c[1]), "+f"(c[2]), "+f"(c[3])
        : "r"(a0), "r"(a1), "r"(a2), "r"(a3), "r"(b0), "r"(b1));
}

// ---------------- 1) gate GEMM (SIMT f32x2) ----------------
__global__ void gate_kernel(const float* __restrict__ x,
                            const float* __restrict__ Wg,
                            const float* __restrict__ bg) {
    __shared__ __align__(16) float As[2][32][132];
    __shared__ __align__(16) float Wgs[2][32][16];

    int tid = threadIdx.x;
    int t0 = blockIdx.x * 128;
    int b  = t0 >> 11;
    int s0 = t0 & 2047;

    int kq = (tid & 7) * 4;
    int am = tid >> 3;
    int kk = tid >> 2;
    int e4 = (tid & 3) * 4;
    int tx = tid & 7;
    int ty = tid >> 3;
    int e0 = tx * 2;
    int m0 = ty * 8;

    ULL acc[4][2];
    #pragma unroll
    for (int p = 0; p < 4; ++p) { acc[p][0] = 0ULL; acc[p][1] = 0ULL; }

    const int nch = DD / 32;
    float4 ra[8];
    float4 rwg;

    #pragma unroll
    for (int p = 0; p < 8; ++p)
        ra[p] = *(const float4*)&x[(size_t)(t0 + am + 16 * p) * DD + kq];
    rwg = *(const float4*)&Wg[(size_t)kk * EE + e4];

    #pragma unroll
    for (int p = 0; p < 8; ++p) {
        int m = am + 16 * p;
        As[0][kq + 0][m] = ra[p].x; As[0][kq + 1][m] = ra[p].y;
        As[0][kq + 2][m] = ra[p].z; As[0][kq + 3][m] = ra[p].w;
    }
    *(float4*)&Wgs[0][kk][e4] = rwg;
    __syncthreads();

    for (int c = 0; c < nch; ++c) {
        int cur = c & 1;
        if (c + 1 < nch) {
            int kc = (c + 1) * 32;
            #pragma unroll
            for (int p = 0; p < 8; ++p)
                ra[p] = *(const float4*)&x[(size_t)(t0 + am + 16 * p) * DD + kc + kq];
            rwg = *(const float4*)&Wg[(size_t)(kc + kk) * EE + e4];
        }
        #pragma unroll
        for (int k = 0; k < 32; ++k) {
            ulonglong2 a01 = *(const ulonglong2*)&As[cur][k][m0];
            ulonglong2 a23 = *(const ulonglong2*)&As[cur][k][m0 + 4];
            float2 wv = *(const float2*)&Wgs[cur][k][e0];
            ULL w0 = dup2(wv.x), w1 = dup2(wv.y);
            fma2(acc[0][0], a01.x, w0); fma2(acc[1][0], a01.y, w0);
            fma2(acc[2][0], a23.x, w0); fma2(acc[3][0], a23.y, w0);
            fma2(acc[0][1], a01.x, w1); fma2(acc[1][1], a01.y, w1);
            fma2(acc[2][1], a23.x, w1); fma2(acc[3][1], a23.y, w1);
        }
        if (c + 1 < nch) {
            int nb = (c + 1) & 1;
            #pragma unroll
            for (int p = 0; p < 8; ++p) {
                int m = am + 16 * p;
                As[nb][kq + 0][m] = ra[p].x; As[nb][kq + 1][m] = ra[p].y;
                As[nb][kq + 2][m] = ra[p].z; As[nb][kq + 3][m] = ra[p].w;
            }
            *(float4*)&Wgs[nb][kk][e4] = rwg;
            __syncthreads();
        }
    }

    #pragma unroll
    for (int j = 0; j < 2; ++j) {
        float bb = bg[e0 + j];
        float* dst = &g_logits[((size_t)(b * EE) + e0 + j) * SS];
        #pragma unroll
        for (int p = 0; p < 4; ++p) {
            float2 v = unpack2(acc[p][j]);
            int s = s0 + m0 + 2 * p;
            *(float2*)&dst[s] = make_float2(v.x + bb, v.y + bb);
        }
    }
}

// ---------------- 2) softmax(+top4) + gather (bf16-split output) ----------------
__global__ void topk_gather_kernel(const float* __restrict__ x) {
    int e = blockIdx.x, b = blockIdx.y;
    __shared__ float sv[SS];
    __shared__ float red[256];
    __shared__ int   redi[256];
    __shared__ float s_max, s_sum;
    __shared__ int   s_idx[KK];
    __shared__ float s_val[KK];
    int tid = threadIdx.x;

    const float* row = &g_logits[(size_t)(b * EE + e) * SS];
    float lmax = -FLT_MAX;
    for (int i = tid; i < SS; i += 256) {
        float v = row[i];
        sv[i] = v;
        lmax = fmaxf(lmax, v);
    }
    red[tid] = lmax;
    __syncthreads();
    for (int off = 128; off > 0; off >>= 1) {
        if (tid < off) red[tid] = fmaxf(red[tid], red[tid + off]);
        __syncthreads();
    }
    if (tid == 0) s_max = red[0];
    __syncthreads();
    float mx = s_max;

    float lsum = 0.f;
    for (int i = tid; i < SS; i += 256) lsum += expf(sv[i] - mx);
    red[tid] = lsum;
    __syncthreads();
    for (int off = 128; off > 0; off >>= 1) {
        if (tid < off) red[tid] += red[tid + off];
        __syncthreads();
    }
    if (tid == 0) s_sum = red[0];
    __syncthreads();
    float inv = 1.0f / s_sum;

    for (int it = 0; it < KK; ++it) {
        float bv = -FLT_MAX;
        int bi = SS;
        for (int i = tid; i < SS; i += 256) {
            float v = sv[i];
            if (v > bv) { bv = v; bi = i; }
        }
        red[tid] = bv; redi[tid] = bi;
        __syncthreads();
        for (int off = 128; off > 0; off >>= 1) {
            if (tid < off) {
                float v2 = red[tid + off]; int i2 = redi[tid + off];
                if (v2 > red[tid] || (v2 == red[tid] && i2 < redi[tid])) {
                    red[tid] = v2; redi[tid] = i2;
                }
            }
            __syncthreads();
        }
        if (tid == 0) {
            int wi = redi[0];
            s_idx[it] = wi;
            s_val[it] = expf(red[0] - mx) * inv;
            sv[wi] = -FLT_MAX;
        }
        __syncthreads();
    }

    // gather, scale, bf16-split -> g_inph / g_inpl [e][b][j*D + d]
    #pragma unroll
    for (int j = 0; j < KK; ++j) {
        int idx = s_idx[j];
        float w = s_val[j];
        const float4* src = (const float4*)&x[((size_t)b * SS + idx) * DD];
        __nv_bfloat16* dh = &g_inph[((size_t)(e * BB + b)) * KD + j * DD];
        __nv_bfloat16* dl = &g_inpl[((size_t)(e * BB + b)) * KD + j * DD];
        int d4 = tid;   // 256 threads, DD/4 = 256 -> exactly one float4 each
        float4 v = src[d4];
        v.x *= w; v.y *= w; v.z *= w; v.w *= w;
        uint32_t h0, l0, h1, l1;
        split2(v.x, v.y, h0, l0);
        split2(v.z, v.w, h1, l1);
        *(uint2*)&dh[d4 * 4] = make_uint2(h0, h1);
        *(uint2*)&dl[d4 * 4] = make_uint2(l0, l1);
    }
}

// ---------------- 3) expert GEMM via mma.sync bf16-split, split-K ----------
// D[b=M32][o=Ntile128] partial sums -> g_part. A = inp hi/lo (bf16, pre-split),
// B = W fp32 -> bf16 hi/lo on the fly. 3 terms: Ah*Bh + Al*Bh + Ah*Bl.
#define A_STRIDE 40    // bf16 elems per row (32 + 8 pad)
#define B_STRIDE 136   // bf16 elems per row (128 + 8 pad)
template<int MODE>
__global__ void __launch_bounds__(128) expert_mma(const float* __restrict__ W, int Ktot) {
    __shared__ __align__(16) __nv_bfloat16 Ah[32 * A_STRIDE];
    __shared__ __align__(16) __nv_bfloat16 Al[32 * A_STRIDE];
    __shared__ __align__(16) __nv_bfloat16 Bh[32 * B_STRIDE];
    __shared__ __align__(16) __nv_bfloat16 Bl[32 * B_STRIDE];

    int e = blockIdx.y, nt = blockIdx.x, ks = blockIdx.z;
    const int Ksub = Ktot / SPLIT;
    const int k0base = ks * Ksub;

    const __nv_bfloat16 *srcH, *srcL;
    if (MODE == 0)      { srcH = g_inph; srcL = g_inpl; }
    else if (MODE == 1) { srcH = g_h1h;  srcL = g_h1l; }
    else                { srcH = g_h2h;  srcL = g_h2l; }
    const __nv_bfloat16* AHg = srcH + (size_t)e * BB * Ktot;
    const __nv_bfloat16* ALg = srcL + (size_t)e * BB * Ktot;
    const float* We = W + (size_t)e * Ktot * OO + nt * 128;
    float* P = g_part + ((size_t)(ks * EE + e) * BB) * OO + nt * 128;

    int tid = threadIdx.x, lane = tid & 31, wid = tid >> 5;
    // staging maps
    int ar = tid >> 2, ac = (tid & 3) * 8;     // A: row b, 8 bf16 (16B)
    int wr = tid >> 2, wc = (tid & 3) * 32;    // W: row k, 32 floats
    // compute map
    int n0 = wid * 32;

    // ldmatrix lane addresses
    uint32_t a_base  = smem_u32(Ah) + ((lane & 15) * A_STRIDE + (lane >> 4) * 8) * 2;
    uint32_t al_base = smem_u32(Al) + ((lane & 15) * A_STRIDE + (lane >> 4) * 8) * 2;
    uint32_t b_base  = smem_u32(Bh) + (lane & 15) * B_STRIDE * 2 + (n0 + (lane >> 4) * 8) * 2;
    uint32_t bl_base = smem_u32(Bl) + (lane & 15) * B_STRIDE * 2 + (n0 + (lane >> 4) * 8) * 2;

    float acc[2][4][4];
    #pragma unroll
    for (int mt = 0; mt < 2; ++mt)
        #pragma unroll
        for (int nf = 0; nf < 4; ++nf)
            #pragma unroll
            for (int q = 0; q < 4; ++q) acc[mt][nf][q] = 0.f;

    const int nch = Ksub >> 5;   // k chunks of 32
    uint4 pah, pal;
    float4 pw[8];

    // prefetch chunk 0
    pah = *(const uint4*)&AHg[(size_t)ar * Ktot + k0base + ac];
    pal = *(const uint4*)&ALg[(size_t)ar * Ktot + k0base + ac];
    #pragma unroll
    for (int i = 0; i < 8; ++i)
        pw[i] = *(const float4*)&We[(size_t)(k0base + wr) * OO + wc + 4 * i];

    for (int c = 0; c < nch; ++c) {
        __syncthreads();   // previous compute done before overwriting smem
        *(uint4*)&Ah[ar * A_STRIDE + ac] = pah;
        *(uint4*)&Al[ar * A_STRIDE + ac] = pal;
        {
            uint32_t wh[16], wl[16];
            #pragma unroll
            for (int i = 0; i < 8; ++i) {
                split2(pw[i].x, pw[i].y, wh[2 * i], wl[2 * i]);
                split2(pw[i].z, pw[i].w, wh[2 * i + 1], wl[2 * i + 1]);
            }
            #pragma unroll
            for (int q = 0; q < 4; ++q) {
                *(uint4*)&Bh[wr * B_STRIDE + wc + 8 * q] = *(uint4*)&wh[4 * q];
                *(uint4*)&Bl[wr * B_STRIDE + wc + 8 * q] = *(uint4*)&wl[4 * q];
            }
        }
        __syncthreads();
        if (c + 1 < nch) {
            int kc = k0base + (c + 1) * 32;
            pah = *(const uint4*)&AHg[(size_t)ar * Ktot + kc + ac];
            pal = *(const uint4*)&ALg[(size_t)ar * Ktot + kc + ac];
            #pragma unroll
            for (int i = 0; i < 8; ++i)
                pw[i] = *(const float4*)&We[(size_t)(kc + wr) * OO + wc + 4 * i];
        }
        #pragma unroll
        for (int ks2 = 0; ks2 < 2; ++ks2) {
            uint32_t ah0[4], ah1[4], alo0[4], alo1[4];
            ldsm4(ah0[0], ah0[1], ah0[2], ah0[3], a_base + ks2 * 32);
            ldsm4(ah1[0], ah1[1], ah1[2], ah1[3], a_base + ks2 * 32 + 16 * A_STRIDE * 2);
            ldsm4(alo0[0], alo0[1], alo0[2], alo0[3], al_base + ks2 * 32);
            ldsm4(alo1[0], alo1[1], alo1[2], alo1[3], al_base + ks2 * 32 + 16 * A_STRIDE * 2);
            uint32_t bh[2][4], bl[2][4];
            #pragma unroll
            for (int j = 0; j < 2; ++j) {
                ldsm4t(bh[j][0], bh[j][1], bh[j][2], bh[j][3], b_base  + ks2 * 16 * B_STRIDE * 2 + j * 32);
                ldsm4t(bl[j][0], bl[j][1], bl[j][2], bl[j][3], bl_base + ks2 * 16 * B_STRIDE * 2 + j * 32);
            }
            #pragma unroll
            for (int mt = 0; mt < 2; ++mt) {
                uint32_t* A0 = mt ? ah1 : ah0;
                uint32_t* A1 = mt ? alo1 : alo0;
                #pragma unroll
                for (int nf = 0; nf < 4; ++nf) {
                    uint32_t b0 = bh[nf >> 1][(nf & 1) * 2];
                    uint32_t b1 = bh[nf >> 1][(nf & 1) * 2 + 1];
                    uint32_t c0 = bl[nf >> 1][(nf & 1) * 2];
                    uint32_t c1 = bl[nf >> 1][(nf & 1) * 2 + 1];
                    mma16816(acc[mt][nf], A0[0], A0[1], A0[2], A0[3], b0, b1);  // Ah*Bh
                    mma16816(acc[mt][nf], A1[0], A1[1], A1[2], A1[3], b0, b1);  // Al*Bh
                    mma16816(acc[mt][nf], A0[0], A0[1], A0[2], A0[3], c0, c1);  // Ah*Bl
                }
            }
        }
    }

    // write partial tile
    #pragma unroll
    for (int mt = 0; mt < 2; ++mt) {
        int r = mt * 16 + (lane >> 2);
        #pragma unroll
        for (int nf = 0; nf < 4; ++nf) {
            int nc = n0 + nf * 8 + (lane & 3) * 2;
            *(float2*)&P[(size_t)r * OO + nc]       = make_float2(acc[mt][nf][0], acc[mt][nf][1]);
            *(float2*)&P[(size_t)(r + 8) * OO + nc] = make_float2(acc[mt][nf][2], acc[mt][nf][3]);
        }
    }
}

// ---------------- 4) split-K reduce: sum + bias (+relu), emit split or final ----
// MODE 0 -> g_h1h/l (relu), MODE 1 -> g_h2h/l (relu), MODE 2 -> out fp32 [b][e][o]
template<int MODE>
__global__ void reduce_kernel(const float* __restrict__ bias, float* __restrict__ outF) {
    int i = blockIdx.x * 256 + threadIdx.x;    // float4 index over E*B*O/4
    int n4 = i & (OO / 4 - 1);
    int m  = (i >> 8) & (BB - 1);
    int e  = i >> 13;

    float4 a = ((const float4*)&g_part[((size_t)e * BB + m) * OO])[n4];
    #pragma unroll
    for (int s = 1; s < SPLIT; ++s) {
        float4 v = ((const float4*)&g_part[((size_t)(s * EE + e) * BB + m) * OO])[n4];
        a.x += v.x; a.y += v.y; a.z += v.z; a.w += v.w;
    }
    float4 bb = ((const float4*)&bias[(size_t)e * OO])[n4];
    a.x += bb.x; a.y += bb.y; a.z += bb.z; a.w += bb.w;
    if (MODE < 2) {
        a.x = fmaxf(a.x, 0.f); a.y = fmaxf(a.y, 0.f);
        a.z = fmaxf(a.z, 0.f); a.w = fmaxf(a.w, 0.f);
        __nv_bfloat16* dh = (MODE == 0) ? g_h1h : g_h2h;
        __nv_bfloat16* dl = (MODE == 0) ? g_h1l : g_h2l;
        size_t off = ((size_t)(e * BB + m)) * OO + n4 * 4;
        uint32_t h0, l0, h1, l1;
        split2(a.x, a.y, h0, l0);
        split2(a.z, a.w, h1, l1);
        *(uint2*)&dh[off] = make_uint2(h0, h1);
        *(uint2*)&dl[off] = make_uint2(l0, l1);
    } else {
        ((float4*)&outF[((size_t)m * EE + e) * OO])[n4] = a;
    }
}

// ---------------- launch ----------------
extern "C" void kernel_launch(void* const* d_in, const int* in_sizes, int n_in,
                              void* d_out, int out_size) {
    const float* x  = (const float*)d_in[0];
    const float* Wg = (const float*)d_in[1];
    const float* bg = (const float*)d_in[2];
    const float* W1 = (const float*)d_in[3];
    const float* b1 = (const float*)d_in[4];
    const float* W2 = (const float*)d_in[5];
    const float* b2 = (const float*)d_in[6];
    const float* W3 = (const float*)d_in[7];
    const float* b3 = (const float*)d_in[8];
    float* out = (float*)d_out;

    const int RED_GRID = (EE * BB * OO / 4) / 256;   // 512

    gate_kernel<<<(BB * SS) / 128, 128>>>(x, Wg, bg);
    topk_gather_kernel<<<dim3(EE, BB), 256>>>(x);

    expert_mma<0><<<dim3(OO / 128, EE, SPLIT), 128>>>(W1, KD);
    reduce_kernel<0><<<RED_GRID, 256>>>(b1, nullptr);

    expert_mma<1><<<dim3(OO / 128, EE, SPLIT), 128>>>(W2, OO);
    reduce_kernel<1><<<RED_GRID, 256>>>(b2, nullptr);

    expert_mma<2><<<dim3(OO / 128, EE, SPLIT), 128>>>(W3, OO);
    reduce_kernel<2><<<RED_GRID, 256>>>(b3, out);
}

// round 6
// speedup vs baseline: 1.5073x; 1.1523x over previous
#include <cuda_runtime.h>
#include <cuda_bf16.h>
#include <float.h>
#include <cstdint>

// Problem constants
#define BB 32
#define SS 2048
#define DD 1024
#define EE 16
#define KK 4
#define OO 1024
#define KD 4096   // KK*DD
#define SPLIT 4

typedef unsigned long long ULL;

// ---------------- scratch (device globals) ----------------
__device__ float g_logits[BB * EE * SS];            // [B][E][S], 4 MB
__device__ __nv_bfloat16 g_inph[EE * BB * KD];      // inp hi, [e][b][4096]
__device__ __nv_bfloat16 g_inpl[EE * BB * KD];      // inp lo
__device__ __nv_bfloat16 g_h1h[EE * BB * OO];
__device__ __nv_bfloat16 g_h1l[EE * BB * OO];
__device__ __nv_bfloat16 g_h2h[EE * BB * OO];
__device__ __nv_bfloat16 g_h2l[EE * BB * OO];
__device__ float g_part[SPLIT * EE * BB * OO];      // split-K partials, 8 MB

// ---------------- f32x2 helpers (gate kernel) ----------------
__device__ __forceinline__ void fma2(ULL& d, ULL a, ULL b) {
    asm("fma.rn.f32x2 %0, %1, %2, %0;" : "+l"(d) : "l"(a), "l"(b));
}
__device__ __forceinline__ ULL dup2(float w) {
    ULL r; asm("mov.b64 %0, {%1, %1};" : "=l"(r) : "f"(w)); return r;
}
__device__ __forceinline__ float2 unpack2(ULL v) {
    float2 f; asm("mov.b64 {%0, %1}, %2;" : "=f"(f.x), "=f"(f.y) : "l"(v)); return f;
}

// ---------------- bf16 split helper ----------------
// packs (a,b): a -> low half, b -> high half; lo = residual
__device__ __forceinline__ void split2(float a, float b, uint32_t& hi, uint32_t& lo) {
    asm("cvt.rn.satfinite.bf16x2.f32 %0, %1, %2;" : "=r"(hi) : "f"(b), "f"(a));
    __nv_bfloat162 hp = *reinterpret_cast<__nv_bfloat162*>(&hi);
    float r0 = a - __low2float(hp);
    float r1 = b - __high2float(hp);
    asm("cvt.rn.satfinite.bf16x2.f32 %0, %1, %2;" : "=r"(lo) : "f"(r1), "f"(r0));
}

// ---------------- portable tensor-core helpers (sm_80+ PTX) ----------------
__device__ __forceinline__ uint32_t smem_u32(const void* p) {
    uint32_t a;
    asm("{ .reg .u64 t; cvta.to.shared.u64 t, %1; cvt.u32.u64 %0, t; }" : "=r"(a) : "l"(p));
    return a;
}
__device__ __forceinline__ void ldsm4(uint32_t& r0, uint32_t& r1, uint32_t& r2, uint32_t& r3, uint32_t addr) {
    asm volatile("ldmatrix.sync.aligned.m8n8.x4.shared.b16 {%0,%1,%2,%3}, [%4];"
        : "=r"(r0), "=r"(r1), "=r"(r2), "=r"(r3) : "r"(addr));
}
__device__ __forceinline__ void mma16816(float* c, uint32_t a0, uint32_t a1, uint32_t a2, uint32_t a3,
                                         uint32_t b0, uint32_t b1) {
    asm("mma.sync.aligned.m16n8k16.row.col.f32.bf16.bf16.f32 "
        "{%0,%1,%2,%3}, {%4,%5,%6,%7}, {%8,%9}, {%0,%1,%2,%3};"
        : "+f"(c[0]), "+f"(c[1]), "+f"(c[2]), "+f"(c[3])
        : "r"(a0), "r"(a1), "r"(a2), "r"(a3), "r"(b0), "r"(b1));
}
__device__ __forceinline__ void cp16(uint32_t smem_dst, const void* gsrc) {
    asm volatile("cp.async.cg.shared.global [%0], [%1], 16;" :: "r"(smem_dst), "l"(gsrc));
}
#define CP_COMMIT() asm volatile("cp.async.commit_group;" ::: "memory")
#define CP_WAIT1()  asm volatile("cp.async.wait_group 1;" ::: "memory")
#define CP_WAIT0()  asm volatile("cp.async.wait_group 0;" ::: "memory")

// ---------------- 1) gate GEMM (SIMT f32x2) ----------------
__global__ void gate_kernel(const float* __restrict__ x,
                            const float* __restrict__ Wg,
                            const float* __restrict__ bg) {
    __shared__ __align__(16) float As[2][32][132];
    __shared__ __align__(16) float Wgs[2][32][16];

    int tid = threadIdx.x;
    int t0 = blockIdx.x * 128;
    int b  = t0 >> 11;
    int s0 = t0 & 2047;

    int kq = (tid & 7) * 4;
    int am = tid >> 3;
    int kk = tid >> 2;
    int e4 = (tid & 3) * 4;
    int tx = tid & 7;
    int ty = tid >> 3;
    int e0 = tx * 2;
    int m0 = ty * 8;

    ULL acc[4][2];
    #pragma unroll
    for (int p = 0; p < 4; ++p) { acc[p][0] = 0ULL; acc[p][1] = 0ULL; }

    const int nch = DD / 32;
    float4 ra[8];
    float4 rwg;

    #pragma unroll
    for (int p = 0; p < 8; ++p)
        ra[p] = *(const float4*)&x[(size_t)(t0 + am + 16 * p) * DD + kq];
    rwg = *(const float4*)&Wg[(size_t)kk * EE + e4];

    #pragma unroll
    for (int p = 0; p < 8; ++p) {
        int m = am + 16 * p;
        As[0][kq + 0][m] = ra[p].x; As[0][kq + 1][m] = ra[p].y;
        As[0][kq + 2][m] = ra[p].z; As[0][kq + 3][m] = ra[p].w;
    }
    *(float4*)&Wgs[0][kk][e4] = rwg;
    __syncthreads();

    for (int c = 0; c < nch; ++c) {
        int cur = c & 1;
        if (c + 1 < nch) {
            int kc = (c + 1) * 32;
            #pragma unroll
            for (int p = 0; p < 8; ++p)
                ra[p] = *(const float4*)&x[(size_t)(t0 + am + 16 * p) * DD + kc + kq];
            rwg = *(const float4*)&Wg[(size_t)(kc + kk) * EE + e4];
        }
        #pragma unroll
        for (int k = 0; k < 32; ++k) {
            ulonglong2 a01 = *(const ulonglong2*)&As[cur][k][m0];
            ulonglong2 a23 = *(const ulonglong2*)&As[cur][k][m0 + 4];
            float2 wv = *(const float2*)&Wgs[cur][k][e0];
            ULL w0 = dup2(wv.x), w1 = dup2(wv.y);
            fma2(acc[0][0], a01.x, w0); fma2(acc[1][0], a01.y, w0);
            fma2(acc[2][0], a23.x, w0); fma2(acc[3][0], a23.y, w0);
            fma2(acc[0][1], a01.x, w1); fma2(acc[1][1], a01.y, w1);
            fma2(acc[2][1], a23.x, w1); fma2(acc[3][1], a23.y, w1);
        }
        if (c + 1 < nch) {
            int nb = (c + 1) & 1;
            #pragma unroll
            for (int p = 0; p < 8; ++p) {
                int m = am + 16 * p;
                As[nb][kq + 0][m] = ra[p].x; As[nb][kq + 1][m] = ra[p].y;
                As[nb][kq + 2][m] = ra[p].z; As[nb][kq + 3][m] = ra[p].w;
            }
            *(float4*)&Wgs[nb][kk][e4] = rwg;
            __syncthreads();
        }
    }

    #pragma unroll
    for (int j = 0; j < 2; ++j) {
        float bb = bg[e0 + j];
        float* dst = &g_logits[((size_t)(b * EE) + e0 + j) * SS];
        #pragma unroll
        for (int p = 0; p < 4; ++p) {
            float2 v = unpack2(acc[p][j]);
            int s = s0 + m0 + 2 * p;
            *(float2*)&dst[s] = make_float2(v.x + bb, v.y + bb);
        }
    }
}

// ---------------- 2) softmax(+top4) + gather (bf16-split output) ----------------
__global__ void topk_gather_kernel(const float* __restrict__ x) {
    int e = blockIdx.x, b = blockIdx.y;
    __shared__ float sv[SS];
    __shared__ float red[256];
    __shared__ int   redi[256];
    __shared__ float s_max, s_sum;
    __shared__ int   s_idx[KK];
    __shared__ float s_val[KK];
    int tid = threadIdx.x;

    const float* row = &g_logits[(size_t)(b * EE + e) * SS];
    float lmax = -FLT_MAX;
    for (int i = tid; i < SS; i += 256) {
        float v = row[i];
        sv[i] = v;
        lmax = fmaxf(lmax, v);
    }
    red[tid] = lmax;
    __syncthreads();
    for (int off = 128; off > 0; off >>= 1) {
        if (tid < off) red[tid] = fmaxf(red[tid], red[tid + off]);
        __syncthreads();
    }
    if (tid == 0) s_max = red[0];
    __syncthreads();
    float mx = s_max;

    float lsum = 0.f;
    for (int i = tid; i < SS; i += 256) lsum += expf(sv[i] - mx);
    red[tid] = lsum;
    __syncthreads();
    for (int off = 128; off > 0; off >>= 1) {
        if (tid < off) red[tid] += red[tid + off];
        __syncthreads();
    }
    if (tid == 0) s_sum = red[0];
    __syncthreads();
    float inv = 1.0f / s_sum;

    for (int it = 0; it < KK; ++it) {
        float bv = -FLT_MAX;
        int bi = SS;
        for (int i = tid; i < SS; i += 256) {
            float v = sv[i];
            if (v > bv) { bv = v; bi = i; }
        }
        red[tid] = bv; redi[tid] = bi;
        __syncthreads();
        for (int off = 128; off > 0; off >>= 1) {
            if (tid < off) {
                float v2 = red[tid + off]; int i2 = redi[tid + off];
                if (v2 > red[tid] || (v2 == red[tid] && i2 < redi[tid])) {
                    red[tid] = v2; redi[tid] = i2;
                }
            }
            __syncthreads();
        }
        if (tid == 0) {
            int wi = redi[0];
            s_idx[it] = wi;
            s_val[it] = expf(red[0] - mx) * inv;
            sv[wi] = -FLT_MAX;
        }
        __syncthreads();
    }

    // gather, scale, bf16-split -> g_inph / g_inpl [e][b][j*D + d]
    #pragma unroll
    for (int j = 0; j < KK; ++j) {
        int idx = s_idx[j];
        float w = s_val[j];
        const float4* src = (const float4*)&x[((size_t)b * SS + idx) * DD];
        __nv_bfloat16* dh = &g_inph[((size_t)(e * BB + b)) * KD + j * DD];
        __nv_bfloat16* dl = &g_inpl[((size_t)(e * BB + b)) * KD + j * DD];
        int d4 = tid;   // 256 threads, DD/4 = 256 -> exactly one float4 each
        float4 v = src[d4];
        v.x *= w; v.y *= w; v.z *= w; v.w *= w;
        uint32_t h0, l0, h1, l1;
        split2(v.x, v.y, h0, l0);
        split2(v.z, v.w, h1, l1);
        *(uint2*)&dh[d4 * 4] = make_uint2(h0, h1);
        *(uint2*)&dl[d4 * 4] = make_uint2(l0, l1);
    }
}

// ---------------- 3) expert GEMM: cp.async 3-stage + mma.sync bf16-split ----
// D[b=M32][o=Ntile128] partial -> g_part. A = inp hi/lo bf16 (ldmatrix),
// W fp32 in smem, converted to bf16 hi/lo at consumption.
// 256 threads = 8 warps, warp-tile 32 x 16.
#define STAGES 3
#define A_STRIDE 40                    // bf16 per A row (32 + 8 pad)
#define W_STRIDE 132                   // floats per W row (128 + 4 pad)
#define WS_BYTES (32 * W_STRIDE * 4)   // 16896 per stage
#define AH_BYTES (32 * A_STRIDE * 2)   // 2560 per stage
#define SM_AH_OFF (STAGES * WS_BYTES)               // 50688
#define SM_AL_OFF (SM_AH_OFF + STAGES * AH_BYTES)   // 58368
#define SM_TOTAL  (SM_AL_OFF + STAGES * AH_BYTES)   // 66048

template<int MODE>
__global__ void __launch_bounds__(256) expert_mma(const float* __restrict__ W, int Ktot) {
    extern __shared__ __align__(16) uint8_t sm[];

    int e = blockIdx.y, nt = blockIdx.x, ks = blockIdx.z;
    const int Ksub = Ktot / SPLIT;
    const int k0base = ks * Ksub;
    const int nch = Ksub >> 5;         // chunks of k=32

    const __nv_bfloat16 *srcH, *srcL;
    if (MODE == 0)      { srcH = g_inph; srcL = g_inpl; }
    else if (MODE == 1) { srcH = g_h1h;  srcL = g_h1l; }
    else                { srcH = g_h2h;  srcL = g_h2l; }
    const __nv_bfloat16* AHg = srcH + (size_t)e * BB * Ktot;
    const __nv_bfloat16* ALg = srcL + (size_t)e * BB * Ktot;
    const float* We = W + (size_t)e * Ktot * OO + nt * 128;
    float* P = g_part + ((size_t)(ks * EE + e) * BB) * OO + nt * 128;

    int tid = threadIdx.x, lane = tid & 31, wid = tid >> 5;
    int n0 = wid * 16;                 // warp col base

    // staging maps
    int wrow = tid >> 3;               // W: row (k), 64 bytes each thread
    int wcol = (tid & 7) * 16;         // float col base
    int arow = (tid & 127) >> 2;       // A: row (b)
    int acol = (tid & 3) * 8;          // bf16 col base

    float acc[2][2][4];
    #pragma unroll
    for (int mt = 0; mt < 2; ++mt)
        #pragma unroll
        for (int nf = 0; nf < 2; ++nf)
            #pragma unroll
            for (int q = 0; q < 4; ++q) acc[mt][nf][q] = 0.f;

    // stage issue helper (cp.async)
    auto issue = [&](int c) {
        int slot = c % STAGES;
        int k0 = k0base + c * 32;
        uint32_t wdst = smem_u32(sm + slot * WS_BYTES) + (wrow * W_STRIDE + wcol) * 4;
        const float* wsrc = &We[(size_t)(k0 + wrow) * OO + wcol];
        #pragma unroll
        for (int i = 0; i < 4; ++i)
            cp16(wdst + i * 16, wsrc + i * 4);
        if (tid < 128) {
            uint32_t adst = smem_u32(sm + SM_AH_OFF + slot * AH_BYTES) + (arow * A_STRIDE + acol) * 2;
            cp16(adst, &AHg[(size_t)arow * Ktot + k0 + acol]);
        } else {
            uint32_t adst = smem_u32(sm + SM_AL_OFF + slot * AH_BYTES) + (arow * A_STRIDE + acol) * 2;
            cp16(adst, &ALg[(size_t)arow * Ktot + k0 + acol]);
        }
        CP_COMMIT();
    };

    issue(0);
    if (nch > 1) issue(1);

    for (int c = 0; c < nch; ++c) {
        if (c + 1 < nch) CP_WAIT1(); else CP_WAIT0();
        __syncthreads();
        if (c + 2 < nch) issue(c + 2);

        int slot = c % STAGES;
        const float* Ws = (const float*)(sm + slot * WS_BYTES);
        uint32_t ah_base = smem_u32(sm + SM_AH_OFF + slot * AH_BYTES) + ((lane & 15) * A_STRIDE + (lane >> 4) * 8) * 2;
        uint32_t al_base = smem_u32(sm + SM_AL_OFF + slot * AH_BYTES) + ((lane & 15) * A_STRIDE + (lane >> 4) * 8) * 2;

        #pragma unroll
        for (int ks2 = 0; ks2 < 2; ++ks2) {
            uint32_t ah0[4], ah1[4], al0[4], al1[4];
            ldsm4(ah0[0], ah0[1], ah0[2], ah0[3], ah_base + ks2 * 32);
            ldsm4(ah1[0], ah1[1], ah1[2], ah1[3], ah_base + ks2 * 32 + 16 * A_STRIDE * 2);
            ldsm4(al0[0], al0[1], al0[2], al0[3], al_base + ks2 * 32);
            ldsm4(al1[0], al1[1], al1[2], al1[3], al_base + ks2 * 32 + 16 * A_STRIDE * 2);
            #pragma unroll
            for (int nf = 0; nf < 2; ++nf) {
                int cc = n0 + nf * 8 + (lane >> 2);
                int kk = ks2 * 16 + (lane & 3) * 2;
                const float* wp = &Ws[kk * W_STRIDE + cc];
                float f0 = wp[0];
                float f1 = wp[W_STRIDE];
                float f2 = wp[8 * W_STRIDE];
                float f3 = wp[9 * W_STRIDE];
                uint32_t b0h, b0l, b1h, b1l;
                split2(f0, f1, b0h, b0l);
                split2(f2, f3, b1h, b1l);
                mma16816(acc[0][nf], ah0[0], ah0[1], ah0[2], ah0[3], b0h, b1h);  // Ah*Bh
                mma16816(acc[1][nf], ah1[0], ah1[1], ah1[2], ah1[3], b0h, b1h);
                mma16816(acc[0][nf], al0[0], al0[1], al0[2], al0[3], b0h, b1h);  // Al*Bh
                mma16816(acc[1][nf], al1[0], al1[1], al1[2], al1[3], b0h, b1h);
                mma16816(acc[0][nf], ah0[0], ah0[1], ah0[2], ah0[3], b0l, b1l);  // Ah*Bl
                mma16816(acc[1][nf], ah1[0], ah1[1], ah1[2], ah1[3], b0l, b1l);
            }
        }
    }

    // write partial tile
    #pragma unroll
    for (int mt = 0; mt < 2; ++mt) {
        int r = mt * 16 + (lane >> 2);
        #pragma unroll
        for (int nf = 0; nf < 2; ++nf) {
            int nc = n0 + nf * 8 + (lane & 3) * 2;
            *(float2*)&P[(size_t)r * OO + nc]       = make_float2(acc[mt][nf][0], acc[mt][nf][1]);
            *(float2*)&P[(size_t)(r + 8) * OO + nc] = make_float2(acc[mt][nf][2], acc[mt][nf][3]);
        }
    }
}

// ---------------- 4) split-K reduce: sum + bias (+relu), emit split or final ----
template<int MODE>
__global__ void reduce_kernel(const float* __restrict__ bias, float* __restrict__ outF) {
    int i = blockIdx.x * 256 + threadIdx.x;    // float4 index over E*B*O/4
    int n4 = i & (OO / 4 - 1);
    int m  = (i >> 8) & (BB - 1);
    int e  = i >> 13;

    float4 a = ((const float4*)&g_part[((size_t)e * BB + m) * OO])[n4];
    #pragma unroll
    for (int s = 1; s < SPLIT; ++s) {
        float4 v = ((const float4*)&g_part[((size_t)(s * EE + e) * BB + m) * OO])[n4];
        a.x += v.x; a.y += v.y; a.z += v.z; a.w += v.w;
    }
    float4 bb = ((const float4*)&bias[(size_t)e * OO])[n4];
    a.x += bb.x; a.y += bb.y; a.z += bb.z; a.w += bb.w;
    if (MODE < 2) {
        a.x = fmaxf(a.x, 0.f); a.y = fmaxf(a.y, 0.f);
        a.z = fmaxf(a.z, 0.f); a.w = fmaxf(a.w, 0.f);
        __nv_bfloat16* dh = (MODE == 0) ? g_h1h : g_h2h;
        __nv_bfloat16* dl = (MODE == 0) ? g_h1l : g_h2l;
        size_t off = ((size_t)(e * BB + m)) * OO + n4 * 4;
        uint32_t h0, l0, h1, l1;
        split2(a.x, a.y, h0, l0);
        split2(a.z, a.w, h1, l1);
        *(uint2*)&dh[off] = make_uint2(h0, h1);
        *(uint2*)&dl[off] = make_uint2(l0, l1);
    } else {
        ((float4*)&outF[((size_t)m * EE + e) * OO])[n4] = a;
    }
}

// ---------------- launch ----------------
extern "C" void kernel_launch(void* const* d_in, const int* in_sizes, int n_in,
                              void* d_out, int out_size) {
    const float* x  = (const float*)d_in[0];
    const float* Wg = (const float*)d_in[1];
    const float* bg = (const float*)d_in[2];
    const float* W1 = (const float*)d_in[3];
    const float* b1 = (const float*)d_in[4];
    const float* W2 = (const float*)d_in[5];
    const float* b2 = (const float*)d_in[6];
    const float* W3 = (const float*)d_in[7];
    const float* b3 = (const float*)d_in[8];
    float* out = (float*)d_out;

    static bool attr_done = false;
    if (!attr_done) {
        cudaFuncSetAttribute(expert_mma<0>, cudaFuncAttributeMaxDynamicSharedMemorySize, SM_TOTAL);
        cudaFuncSetAttribute(expert_mma<1>, cudaFuncAttributeMaxDynamicSharedMemorySize, SM_TOTAL);
        cudaFuncSetAttribute(expert_mma<2>, cudaFuncAttributeMaxDynamicSharedMemorySize, SM_TOTAL);
        attr_done = true;
    }

    const int RED_GRID = (EE * BB * OO / 4) / 256;   // 512

    gate_kernel<<<(BB * SS) / 128, 128>>>(x, Wg, bg);
    topk_gather_kernel<<<dim3(EE, BB), 256>>>(x);

    expert_mma<0><<<dim3(OO / 128, EE, SPLIT), 256, SM_TOTAL>>>(W1, KD);
    reduce_kernel<0><<<RED_GRID, 256>>>(b1, nullptr);

    expert_mma<1><<<dim3(OO / 128, EE, SPLIT), 256, SM_TOTAL>>>(W2, OO);
    reduce_kernel<1><<<RED_GRID, 256>>>(b2, nullptr);

    expert_mma<2><<<dim3(OO / 128, EE, SPLIT), 256, SM_TOTAL>>>(W3, OO);
    reduce_kernel<2><<<RED_GRID, 256>>>(b3, out);
}